// round 16
// baseline (speedup 1.0000x reference)
#include <cuda_runtime.h>
#include <cstdint>
#include <math.h>

// NT_Xent collapsed: neg_n = (r_n/||r_n||) . S / T,  S = sum_m mem_m/||mem_m||.
// TWO kernels (graph-captured back to back):
//  K1: R1's verbatim bank-reduce (512thr x 148 blocks, regs~40) with ONE
//      change: __ldcs (evict-first streaming) on the bank loads. The bank is
//      read once; default allocation churns L2 on a 32MB stream.
//  K2: unchanged from R15 (prefetched row loads, fully-unrolled S rebuild,
//      one loss row per warp, last-arriving block -> mean, counter reset).
// All reductions are fixed-order trees -> deterministic.

#define D      128
#define DV     32            // float4 per row
#define B1     148
#define T1     512
#define NW1    (T1 / 32)     // 16 warps
#define B2     64
#define T2     512
#define NW2    (T2 / 32)     // 16 warps
#define INV_T  10.0f
#define EPSN   1e-8f

__device__ float        g_partialS[B1 * D];
__device__ float        g_partialLoss[B2];
__device__ unsigned int g_cnt = 0;

__device__ __forceinline__ float warp_sum(float v) {
    #pragma unroll
    for (int o = 16; o > 0; o >>= 1) v += __shfl_xor_sync(0xffffffffu, v, o);
    return v;
}
__device__ __forceinline__ float dot4(float4 a, float4 b) {
    return a.x * b.x + a.y * b.y + a.z * b.z + a.w * b.w;
}

// ---------------- K1: memory-bank reduction (R1 + __ldcs) ----------------
__global__ __launch_bounds__(T1) void bank_reduce_kernel(const float4* __restrict__ mem, int M) {
    const int tid  = threadIdx.x;
    const int w    = tid >> 5;
    const int lane = tid & 31;
    const int gw   = blockIdx.x * NW1 + w;     // global warp id
    const int W    = B1 * NW1;                 // total warps

    float4 acc = make_float4(0.f, 0.f, 0.f, 0.f);

    const int iters = (M + W - 1) / W;         // rows per warp (ceil)
    for (int k = 0; k < iters; k += 4) {
        float4 v[4];
        #pragma unroll
        for (int u = 0; u < 4; u++) {
            int m = gw + (k + u) * W;
            v[u] = (m < M) ? __ldcs(mem + (size_t)m * DV + lane)
                           : make_float4(0.f, 0.f, 0.f, 0.f);
        }
        #pragma unroll
        for (int u = 0; u < 4; u++) {
            float s = v[u].x * v[u].x + v[u].y * v[u].y
                    + v[u].z * v[u].z + v[u].w * v[u].w;
            s = warp_sum(s);
            float inv = 1.0f / fmaxf(sqrtf(s), EPSN);  // zero rows contribute 0
            acc.x += v[u].x * inv;
            acc.y += v[u].y * inv;
            acc.z += v[u].z * inv;
            acc.w += v[u].w * inv;
        }
    }

    __shared__ float4 sacc[NW1][32];
    sacc[w][lane] = acc;
    __syncthreads();

    if (tid < D) {
        float s = 0.f;
        #pragma unroll
        for (int ww = 0; ww < NW1; ww++)
            s += ((const float*)sacc[ww])[tid];
        g_partialS[blockIdx.x * D + tid] = s;
    }
}

// ---------------- K2: prefetch rows + unrolled S rebuild + loss ----------------
__global__ __launch_bounds__(T2) void loss_kernel(const float4* __restrict__ real,
                                                  const float4* __restrict__ pert,
                                                  int N, float* __restrict__ out) {
    __shared__ float Sq[4][D];
    __shared__ float S[D];
    __shared__ float wsum[NW2];
    __shared__ int   islast;

    const int tid  = threadIdx.x;
    const int w    = tid >> 5;
    const int lane = tid & 31;
    const int bid  = blockIdx.x;
    const int n    = bid * NW2 + w;          // 64*16 = 1024 rows, each once

    // ---- 1) issue per-row loads FIRST (latency hides behind S rebuild) ----
    float4 rv = make_float4(0.f, 0.f, 0.f, 0.f);
    float4 pv = make_float4(0.f, 0.f, 0.f, 0.f);
    if (n < N) {
        rv = real[(size_t)n * DV + lane];
        pv = pert[(size_t)n * DV + lane];
    }

    // ---- 2) rebuild S: fully unrolled 37-trip loop (148 = 4*37) ----
    {
        const int col = tid & (D - 1);
        const int q   = tid >> 7;            // 0..3
        float s = 0.f;
        #pragma unroll
        for (int j = 0; j < B1 / 4; j++)     // 37 independent loads in flight
            s += g_partialS[(q + 4 * j) * D + col];
        Sq[q][col] = s;
    }
    __syncthreads();
    if (tid < D) {
        float t = 0.f;
        #pragma unroll
        for (int j = 0; j < 4; j++) t += Sq[j][tid];
        S[tid] = t;
    }
    __syncthreads();

    const float4 s4 = ((const float4*)S)[lane];

    // ---- 3) loss: 4 independent butterflies (ILP) ----
    float lsum = 0.f;
    if (n < N) {
        float rr = dot4(rv, rv);
        float pp = dot4(pv, pv);
        float rp = dot4(rv, pv);
        float rs = dot4(rv, s4);
        #pragma unroll
        for (int o = 16; o > 0; o >>= 1) {
            rr += __shfl_xor_sync(0xffffffffu, rr, o);
            pp += __shfl_xor_sync(0xffffffffu, pp, o);
            rp += __shfl_xor_sync(0xffffffffu, rp, o);
            rs += __shfl_xor_sync(0xffffffffu, rs, o);
        }
        if (lane == 0) {
            float rn  = fmaxf(sqrtf(rr), EPSN);
            float pn  = fmaxf(sqrtf(pp), EPSN);
            float pos = rp / (rn * pn) * INV_T;
            float neg = rs / rn * INV_T;
            float mx  = fmaxf(pos, neg);
            float lse = mx + logf(expf(pos - mx) + expf(neg - mx));
            lsum = lse - pos;                // -log_softmax[0]
        }
    }
    if (lane == 0) wsum[w] = lsum;
    __syncthreads();

    if (tid == 0) {
        float b = 0.f;
        #pragma unroll
        for (int ww = 0; ww < NW2; ww++) b += wsum[ww];
        g_partialLoss[bid] = b;
        __threadfence();
        unsigned int ret = atomicAdd(&g_cnt, 1u);
        islast = (ret == B2 - 1) ? 1 : 0;
    }
    __syncthreads();

    // last-arriving block: fixed-order 64->1 reduce, write mean, reset counter
    if (islast && w == 0) {
        __threadfence();
        float v = 0.f;
        #pragma unroll
        for (int j = 0; j < B2 / 32; j++)
            v += g_partialLoss[lane + 32 * j];
        v = warp_sum(v);
        if (lane == 0) {
            out[0] = v / (float)N;
            g_cnt = 0;
        }
    }
}

extern "C" void kernel_launch(void* const* d_in, const int* in_sizes, int n_in,
                              void* d_out, int out_size) {
    const float4* real = (const float4*)d_in[0];
    const float4* pert = (const float4*)d_in[1];
    const float4* mem  = (const float4*)d_in[2];
    int N = in_sizes[0] / D;
    int M = in_sizes[2] / D;

    bank_reduce_kernel<<<B1, T1>>>(mem, M);
    loss_kernel<<<B2, T2>>>(real, pert, N, (float*)d_out);
}

// round 17
// speedup vs baseline: 1.0152x; 1.0152x over previous
#include <cuda_runtime.h>
#include <cstdint>
#include <math.h>

// NT_Xent collapsed: neg_n = (r_n/||r_n||) . S / T,  S = sum_m mem_m/||mem_m||.
// TWO kernels (graph-captured back to back):
//  K1: R1's verbatim bank-reduce loop (512thr x 148 blocks, the only shape
//      that reaches ~2.5TB/s) -> g_partialS[148][128]. AFTER the stream, warp
//      gw < N also precomputes the S-independent loss pieces: pos[n] and the
//      normalized row rhat[n] (overlaps straggler blocks' streaming).
//  K2: short tail: prefetch rhat, rebuild S (37-deep unrolled), ONE shfl
//      chain rs = rhat.S, loss = lse(pos, rs/T) - pos; last-arriving block
//      reduces 64 partials -> mean -> out, resets counter (replay safe).
// All reductions are fixed-order trees -> deterministic.

#define D      128
#define DV     32            // float4 per row
#define B1     148
#define T1     512
#define NW1    (T1 / 32)     // 16 warps
#define B2     64
#define T2     512
#define NW2    (T2 / 32)     // 16 warps
#define NMAX   1024
#define INV_T  10.0f
#define EPSN   1e-8f

__device__ float        g_partialS[B1 * D];
__device__ float4       g_rhat[NMAX * DV];    // normalized real rows (512KB)
__device__ float        g_pos[NMAX];
__device__ float        g_partialLoss[B2];
__device__ unsigned int g_cnt = 0;

__device__ __forceinline__ float warp_sum(float v) {
    #pragma unroll
    for (int o = 16; o > 0; o >>= 1) v += __shfl_xor_sync(0xffffffffu, v, o);
    return v;
}
__device__ __forceinline__ float dot4(float4 a, float4 b) {
    return a.x * b.x + a.y * b.y + a.z * b.z + a.w * b.w;
}

// ---------------- K1: bank reduction (R1 verbatim) + pos/rhat precompute ----------------
__global__ __launch_bounds__(T1) void bank_reduce_kernel(const float4* __restrict__ mem, int M,
                                                         const float4* __restrict__ real,
                                                         const float4* __restrict__ pert, int N) {
    const int tid  = threadIdx.x;
    const int w    = tid >> 5;
    const int lane = tid & 31;
    const int gw   = blockIdx.x * NW1 + w;     // global warp id
    const int W    = B1 * NW1;                 // total warps

    float4 acc = make_float4(0.f, 0.f, 0.f, 0.f);

    const int iters = (M + W - 1) / W;         // rows per warp (ceil)
    for (int k = 0; k < iters; k += 4) {
        float4 v[4];
        #pragma unroll
        for (int u = 0; u < 4; u++) {
            int m = gw + (k + u) * W;
            v[u] = (m < M) ? mem[(size_t)m * DV + lane]
                           : make_float4(0.f, 0.f, 0.f, 0.f);
        }
        #pragma unroll
        for (int u = 0; u < 4; u++) {
            float s = v[u].x * v[u].x + v[u].y * v[u].y
                    + v[u].z * v[u].z + v[u].w * v[u].w;
            s = warp_sum(s);
            float inv = 1.0f / fmaxf(sqrtf(s), EPSN);  // zero rows contribute 0
            acc.x += v[u].x * inv;
            acc.y += v[u].y * inv;
            acc.z += v[u].z * inv;
            acc.w += v[u].w * inv;
        }
    }

    __shared__ float4 sacc[NW1][32];
    sacc[w][lane] = acc;
    __syncthreads();

    if (tid < D) {
        float s = 0.f;
        #pragma unroll
        for (int ww = 0; ww < NW1; ww++)
            s += ((const float*)sacc[ww])[tid];
        g_partialS[blockIdx.x * D + tid] = s;
    }

    // ---- S-independent loss pieces (overlaps straggler blocks' streaming) ----
    if (gw < N) {
        float4 rv = real[(size_t)gw * DV + lane];
        float4 pv = pert[(size_t)gw * DV + lane];
        float rr = dot4(rv, rv);
        float pp = dot4(pv, pv);
        float rp = dot4(rv, pv);
        #pragma unroll
        for (int o = 16; o > 0; o >>= 1) {
            rr += __shfl_xor_sync(0xffffffffu, rr, o);
            pp += __shfl_xor_sync(0xffffffffu, pp, o);
            rp += __shfl_xor_sync(0xffffffffu, rp, o);
        }
        float rn  = fmaxf(sqrtf(rr), EPSN);
        float pn  = fmaxf(sqrtf(pp), EPSN);
        float inv = 1.0f / rn;
        float4 rh = make_float4(rv.x * inv, rv.y * inv, rv.z * inv, rv.w * inv);
        g_rhat[(size_t)gw * DV + lane] = rh;
        if (lane == 0)
            g_pos[gw] = rp / (rn * pn) * INV_T;
    }
}

// ---------------- K2: short tail ----------------
__global__ __launch_bounds__(T2) void loss_kernel(int N, float* __restrict__ out) {
    __shared__ float Sq[4][D];
    __shared__ float S[D];
    __shared__ float wsum[NW2];
    __shared__ int   islast;

    const int tid  = threadIdx.x;
    const int w    = tid >> 5;
    const int lane = tid & 31;
    const int bid  = blockIdx.x;
    const int n    = bid * NW2 + w;          // 64*16 = 1024 rows, each once

    // ---- 1) prefetch rhat (latency hides behind S rebuild) ----
    float4 rh = make_float4(0.f, 0.f, 0.f, 0.f);
    if (n < N) rh = g_rhat[(size_t)n * DV + lane];

    // ---- 2) rebuild S: fully unrolled 37-trip loop (148 = 4*37) ----
    {
        const int col = tid & (D - 1);
        const int q   = tid >> 7;            // 0..3
        float s = 0.f;
        #pragma unroll
        for (int j = 0; j < B1 / 4; j++)     // 37 independent loads in flight
            s += g_partialS[(q + 4 * j) * D + col];
        Sq[q][col] = s;
    }
    __syncthreads();
    if (tid < D) {
        float t = 0.f;
        #pragma unroll
        for (int j = 0; j < 4; j++) t += Sq[j][tid];
        S[tid] = t;
    }
    __syncthreads();

    const float4 s4 = ((const float4*)S)[lane];

    // ---- 3) loss: single reduction + lse ----
    float lsum = 0.f;
    if (n < N) {
        float rs = warp_sum(dot4(rh, s4));
        if (lane == 0) {
            float pos = g_pos[n];
            float neg = rs * INV_T;
            float mx  = fmaxf(pos, neg);
            float lse = mx + logf(expf(pos - mx) + expf(neg - mx));
            lsum = lse - pos;                // -log_softmax[0]
        }
    }
    if (lane == 0) wsum[w] = lsum;
    __syncthreads();

    if (tid == 0) {
        float b = 0.f;
        #pragma unroll
        for (int ww = 0; ww < NW2; ww++) b += wsum[ww];
        g_partialLoss[bid] = b;
        __threadfence();
        unsigned int ret = atomicAdd(&g_cnt, 1u);
        islast = (ret == B2 - 1) ? 1 : 0;
    }
    __syncthreads();

    // last-arriving block: fixed-order 64->1 reduce, write mean, reset counter
    if (islast && w == 0) {
        __threadfence();
        float v = 0.f;
        #pragma unroll
        for (int j = 0; j < B2 / 32; j++)
            v += g_partialLoss[lane + 32 * j];
        v = warp_sum(v);
        if (lane == 0) {
            out[0] = v / (float)N;
            g_cnt = 0;
        }
    }
}

extern "C" void kernel_launch(void* const* d_in, const int* in_sizes, int n_in,
                              void* d_out, int out_size) {
    const float4* real = (const float4*)d_in[0];
    const float4* pert = (const float4*)d_in[1];
    const float4* mem  = (const float4*)d_in[2];
    int N = in_sizes[0] / D;
    int M = in_sizes[2] / D;

    bank_reduce_kernel<<<B1, T1>>>(mem, M, real, pert, N);
    loss_kernel<<<B2, T2>>>(N, (float*)d_out);
}